// round 3
// baseline (speedup 1.0000x reference)
#include <cuda_runtime.h>
#include <cstdint>
#include <cstddef>

#define T_STEPS 1024
#define BATCH   256
#define IDIM    128
#define HDIM    128
#define NCLS    18
#define G4      (4*HDIM)              /* 512 */
#define M_TOT   (T_STEPS*BATCH)       /* 262144 */

#define RSM   416                     /* W_hh rows resident in SMEM */
#define WPAD  132                     /* padded row stride (floats); 33 odd -> conflict-free f4 */

/* Scratch (allocation-free rule: __device__ globals). */
__device__ float g_P[(size_t)M_TOT * G4];   /* 512 MB pre-gates */
__device__ float g_h[(size_t)M_TOT * HDIM]; /* 128 MB h_all    */

/* ------------------------------------------------------------------ */
/* Kernel 1: P = X @ W_ih^T + (b_ih + b_hh).  M=262144, N=512, K=128. */
/* Tiles 64x64, full K in SMEM (k-major, stride 68), 256 thr, 4x4/thr */
/* ------------------------------------------------------------------ */
__global__ __launch_bounds__(256) void k_input_gemm(
    const float* __restrict__ X, const float* __restrict__ Wih,
    const float* __restrict__ bih, const float* __restrict__ bhh)
{
    extern __shared__ float sm1[];
    float* Xs = sm1;                 /* [128][68] k-major */
    float* Ws = sm1 + 128 * 68;      /* [128][68] k-major */

    const int tid = threadIdx.x;
    const int m0 = blockIdx.y * 64;
    const int n0 = blockIdx.x * 64;

    for (int idx = tid; idx < 64 * 128; idx += 256) {
        int r = idx >> 7, k = idx & 127;
        Xs[k * 68 + r] = X[(size_t)(m0 + r) * IDIM + k];
        Ws[k * 68 + r] = Wih[(size_t)(n0 + r) * IDIM + k];
    }
    __syncthreads();

    const int tx = tid & 15, ty = tid >> 4;
    float acc[4][4];
#pragma unroll
    for (int i = 0; i < 4; i++)
#pragma unroll
        for (int jj = 0; jj < 4; jj++) acc[i][jj] = 0.f;

#pragma unroll 8
    for (int k = 0; k < 128; k++) {
        float4 a = *(const float4*)&Xs[k * 68 + ty * 4];
        float4 b = *(const float4*)&Ws[k * 68 + tx * 4];
        float av[4] = {a.x, a.y, a.z, a.w};
        float bv[4] = {b.x, b.y, b.z, b.w};
#pragma unroll
        for (int i = 0; i < 4; i++)
#pragma unroll
            for (int jj = 0; jj < 4; jj++) acc[i][jj] += av[i] * bv[jj];
    }

    float bsv[4];
#pragma unroll
    for (int jj = 0; jj < 4; jj++)
        bsv[jj] = __ldg(&bih[n0 + tx * 4 + jj]) + __ldg(&bhh[n0 + tx * 4 + jj]);

#pragma unroll
    for (int i = 0; i < 4; i++) {
        float4 v = make_float4(acc[i][0] + bsv[0], acc[i][1] + bsv[1],
                               acc[i][2] + bsv[2], acc[i][3] + bsv[3]);
        *(float4*)&g_P[(size_t)(m0 + ty * 4 + i) * G4 + n0 + tx * 4] = v;
    }
}

/* ------------------------------------------------------------------ */
/* Kernel 2: recurrence. 128 CTAs x 512 threads; CTA owns 2 batch els */
/* Thread j computes gate row j for both batch elements each step.    */
/* W_hh rows [0,RSM) in SMEM; rows [RSM,512) (warps 13-15) from L2.   */
/* ------------------------------------------------------------------ */
__global__ __launch_bounds__(512) void k_lstm(
    const float* __restrict__ h0, const float* __restrict__ c0,
    const float* __restrict__ Whh, float* __restrict__ state_out,
    int write_state)
{
    extern __shared__ float sm2[];
    float* Wsm   = sm2;                    /* RSM * WPAD          */
    float* gates = Wsm + RSM * WPAD;       /* [2][512]            */
    float* hb    = gates + 2 * G4;         /* [2 bufs][2 b][128]  */
    float* cs    = hb + 512;               /* [2][128]            */

    const int tid = threadIdx.x;
    const int b0  = blockIdx.x * 2;

    for (int idx = tid; idx < RSM * HDIM; idx += 512) {
        int j = idx >> 7, k = idx & 127;
        Wsm[j * WPAD + k] = Whh[idx];
    }
    if (tid < 256) {
        int bb = tid >> 7, u = tid & 127;
        hb[bb * 128 + u] = h0[(b0 + bb) * HDIM + u];
        cs[bb * 128 + u] = c0[(b0 + bb) * HDIM + u];
    }
    __syncthreads();

    const int j = tid;
    size_t ip = (size_t)b0 * G4 + j;
    float p0 = g_P[ip], p1 = g_P[ip + G4];

    const float4* wg4 = (const float4*)(Whh + (size_t)j * HDIM); /* global row */
    const float4* ws4 = (const float4*)(Wsm + j * WPAD);         /* smem row   */

    for (int t = 0; t < T_STEPS; t++) {
        float pa = p0, pb = p1;
        ip += (size_t)BATCH * G4;
        if (t < T_STEPS - 1) { p0 = g_P[ip]; p1 = g_P[ip + G4]; } /* prefetch */

        const float4* hc = (const float4*)(hb + (t & 1) * 256);
        float a0 = 0, a1 = 0, a2 = 0, a3 = 0;
        float d0 = 0, d1 = 0, d2 = 0, d3 = 0;

        if (j < RSM) {
#pragma unroll 8
            for (int kk = 0; kk < 32; kk++) {
                float4 w  = ws4[kk];
                float4 ha = hc[kk];
                float4 hd = hc[32 + kk];
                a0 += w.x * ha.x; a1 += w.y * ha.y; a2 += w.z * ha.z; a3 += w.w * ha.w;
                d0 += w.x * hd.x; d1 += w.y * hd.y; d2 += w.z * hd.z; d3 += w.w * hd.w;
            }
        } else {
#pragma unroll 8
            for (int kk = 0; kk < 32; kk++) {
                float4 w  = __ldg(&wg4[kk]);
                float4 ha = hc[kk];
                float4 hd = hc[32 + kk];
                a0 += w.x * ha.x; a1 += w.y * ha.y; a2 += w.z * ha.z; a3 += w.w * ha.w;
                d0 += w.x * hd.x; d1 += w.y * hd.y; d2 += w.z * hd.z; d3 += w.w * hd.w;
            }
        }
        gates[j]      = pa + ((a0 + a1) + (a2 + a3));
        gates[G4 + j] = pb + ((d0 + d1) + (d2 + d3));
        __syncthreads();

        if (tid < 256) {
            int bb = tid >> 7, u = tid & 127;
            const float* gb = gates + bb * G4;
            float gi = gb[u], gf = gb[128 + u], gg = gb[256 + u], go = gb[384 + u];
            float iv = 1.f / (1.f + __expf(-gi));
            float fv = 1.f / (1.f + __expf(-gf));
            float gv = tanhf(gg);
            float ov = 1.f / (1.f + __expf(-go));
            float c  = fv * cs[bb * 128 + u] + iv * gv;
            float h  = ov * tanhf(c);
            cs[bb * 128 + u] = c;
            hb[((t + 1) & 1) * 256 + bb * 128 + u] = h;
            g_h[((size_t)t * BATCH + b0 + bb) * HDIM + u] = h;
            if (write_state && t == T_STEPS - 1) {
                state_out[(b0 + bb) * HDIM + u]                = h;
                state_out[BATCH * HDIM + (b0 + bb) * HDIM + u] = c;
            }
        }
        __syncthreads();
    }
}

/* ------------------------------------------------------------------ */
/* Kernel 3: out = h_all @ fc_W^T + fc_b. One (t,b) row per thread.   */
/* ------------------------------------------------------------------ */
__global__ __launch_bounds__(256) void k_fc(
    const float* __restrict__ fcW, const float* __restrict__ fcb,
    float* __restrict__ out)
{
    __shared__ float Ws[NCLS * HDIM];
    __shared__ float bs[NCLS];
    const int tid = threadIdx.x;
    for (int i = tid; i < NCLS * HDIM; i += 256) Ws[i] = fcW[i];
    if (tid < NCLS) bs[tid] = fcb[tid];
    __syncthreads();

    const size_t m = (size_t)blockIdx.x * 256 + tid;
    const float4* hv = (const float4*)(g_h + m * HDIM);
    float acc[NCLS];
#pragma unroll
    for (int c = 0; c < NCLS; c++) acc[c] = bs[c];

#pragma unroll 2
    for (int kk = 0; kk < 32; kk++) {
        float4 h = __ldg(&hv[kk]);
#pragma unroll
        for (int c = 0; c < NCLS; c++) {
            float4 w = *(const float4*)&Ws[c * HDIM + kk * 4];
            acc[c] += h.x * w.x + h.y * w.y + h.z * w.z + h.w * w.w;
        }
    }
    float* po = out + m * NCLS;
#pragma unroll
    for (int c = 0; c < NCLS; c++) po[c] = acc[c];
}

/* ------------------------------------------------------------------ */
extern "C" void kernel_launch(void* const* d_in, const int* in_sizes, int n_in,
                              void* d_out, int out_size)
{
    const float* X   = (const float*)d_in[0];
    const float* hid = (const float*)d_in[1];
    const float* cel = (const float*)d_in[2];
    const float* Wih = (const float*)d_in[3];
    const float* Whh = (const float*)d_in[4];
    const float* bih = (const float*)d_in[5];
    const float* bhh = (const float*)d_in[6];
    const float* fcW = (const float*)d_in[7];
    const float* fcb = (const float*)d_in[8];
    float* out = (float*)d_out;

    const int smem1 = 2 * 128 * 68 * 4;                          /* 69632  */
    const int smem2 = (RSM * WPAD + 2 * G4 + 512 + 256) * 4;     /* 226816 */
    cudaFuncSetAttribute(k_input_gemm, cudaFuncAttributeMaxDynamicSharedMemorySize, smem1);
    cudaFuncSetAttribute(k_lstm,       cudaFuncAttributeMaxDynamicSharedMemorySize, smem2);

    k_input_gemm<<<dim3(G4 / 64, M_TOT / 64), 256, smem1>>>(X, Wih, bih, bhh);

    const int main_elems = T_STEPS * BATCH * NCLS;
    int wstate = (out_size >= main_elems + 2 * BATCH * HDIM) ? 1 : 0;
    float* state_out = out + (size_t)main_elems;
    k_lstm<<<BATCH / 2, 512, smem2>>>(hid, cel, Whh, state_out, wstate);

    k_fc<<<M_TOT / 256, 256>>>(fcW, fcb, out);
}

// round 4
// speedup vs baseline: 3.6151x; 3.6151x over previous
#include <cuda_runtime.h>
#include <cstdint>
#include <cstddef>

#define T_STEPS 1024
#define BATCH   256
#define IDIM    128
#define HDIM    128
#define NCLS    18
#define G4      (4*HDIM)              /* 512 */
#define M_TOT   (T_STEPS*BATCH)       /* 262144 */

typedef unsigned long long ull;

/* Scratch (allocation-free rule: __device__ globals). */
__device__ float g_P[(size_t)M_TOT * G4];   /* 512 MB pre-gates */
__device__ float g_h[(size_t)M_TOT * HDIM]; /* 128 MB h_all    */

/* packed f32x2 FMA: d = a*b + d  (two fp32 lanes per instruction) */
__device__ __forceinline__ void ffma2(ull& d, ull a, ull b) {
    asm("fma.rn.f32x2 %0, %1, %2, %0;" : "+l"(d) : "l"(a), "l"(b));
}
__device__ __forceinline__ float hsum2(ull v) {
    float2 f = *(float2*)&v;
    return f.x + f.y;
}

/* ------------------------------------------------------------------ */
/* Kernel 1: P = X @ W_ih^T + (b_ih + b_hh).  M=262144, N=512, K=128. */
/* (unchanged from R1 — tensor-core rewrite is the next-round target) */
/* ------------------------------------------------------------------ */
__global__ __launch_bounds__(256) void k_input_gemm(
    const float* __restrict__ X, const float* __restrict__ Wih,
    const float* __restrict__ bih, const float* __restrict__ bhh)
{
    extern __shared__ float sm1[];
    float* Xs = sm1;                 /* [128][68] k-major */
    float* Ws = sm1 + 128 * 68;      /* [128][68] k-major */

    const int tid = threadIdx.x;
    const int m0 = blockIdx.y * 64;
    const int n0 = blockIdx.x * 64;

    for (int idx = tid; idx < 64 * 128; idx += 256) {
        int r = idx >> 7, k = idx & 127;
        Xs[k * 68 + r] = X[(size_t)(m0 + r) * IDIM + k];
        Ws[k * 68 + r] = Wih[(size_t)(n0 + r) * IDIM + k];
    }
    __syncthreads();

    const int tx = tid & 15, ty = tid >> 4;
    float acc[4][4];
#pragma unroll
    for (int i = 0; i < 4; i++)
#pragma unroll
        for (int jj = 0; jj < 4; jj++) acc[i][jj] = 0.f;

#pragma unroll 8
    for (int k = 0; k < 128; k++) {
        float4 a = *(const float4*)&Xs[k * 68 + ty * 4];
        float4 b = *(const float4*)&Ws[k * 68 + tx * 4];
        float av[4] = {a.x, a.y, a.z, a.w};
        float bv[4] = {b.x, b.y, b.z, b.w};
#pragma unroll
        for (int i = 0; i < 4; i++)
#pragma unroll
            for (int jj = 0; jj < 4; jj++) acc[i][jj] += av[i] * bv[jj];
    }

    float bsv[4];
#pragma unroll
    for (int jj = 0; jj < 4; jj++)
        bsv[jj] = __ldg(&bih[n0 + tx * 4 + jj]) + __ldg(&bhh[n0 + tx * 4 + jj]);

#pragma unroll
    for (int i = 0; i < 4; i++) {
        float4 v = make_float4(acc[i][0] + bsv[0], acc[i][1] + bsv[1],
                               acc[i][2] + bsv[2], acc[i][3] + bsv[3]);
        *(float4*)&g_P[(size_t)(m0 + ty * 4 + i) * G4 + n0 + tx * 4] = v;
    }
}

/* ------------------------------------------------------------------ */
/* Kernel 2 (redesigned): 128 CTAs x 256 threads; CTA owns 2 batches. */
/* Thread tid owns gate rows tid and tid+256.                         */
/* W_hh k=0..63 lives in REGISTERS (128 regs/thread = 128KB/CTA),     */
/* W_hh k=64..127 lives in SMEM (conflict-free, stride 68).           */
/* All math uses packed fma.rn.f32x2 over k-pairs.                    */
/* ------------------------------------------------------------------ */
__global__ __launch_bounds__(256, 1) void k_lstm(
    const float* __restrict__ h0, const float* __restrict__ c0,
    const float* __restrict__ Whh, float* __restrict__ state_out,
    int write_state)
{
    extern __shared__ float sm2[];
    float* Wsm  = sm2;                  /* 512 rows x 68 (k=64..127 in cols 0..63) */
    float* hbuf = Wsm + 512 * 68;       /* [2 bufs][2 batch][128]                  */
    float* gsm  = hbuf + 512;           /* [512 rows][2 batch]                     */

    const int tid = threadIdx.x;
    const int b0  = blockIdx.x * 2;

    /* load SMEM half of W: rows 0..511, k=64..127 */
    for (int idx = tid; idx < 512 * 16; idx += 256) {
        int row = idx >> 4, q = idx & 15;
        *(float4*)&Wsm[row * 68 + 4 * q] =
            *(const float4*)&Whh[(size_t)row * 128 + 64 + 4 * q];
    }

    /* register half of W: rows tid and tid+256, k=0..63, packed as f32x2 */
    ull w0[32], w1[32];
    {
        const ulonglong2* wg0 = (const ulonglong2*)(Whh + (size_t)tid * 128);
        const ulonglong2* wg1 = (const ulonglong2*)(Whh + (size_t)(tid + 256) * 128);
#pragma unroll
        for (int q = 0; q < 16; q++) {
            ulonglong2 t0 = wg0[q]; w0[2 * q] = t0.x; w0[2 * q + 1] = t0.y;
            ulonglong2 t1 = wg1[q]; w1[2 * q] = t1.x; w1[2 * q + 1] = t1.y;
        }
    }

    /* init h (smem buf 0) and c (register of epilogue-owner thread) */
    const int eb = tid >> 7, eu = tid & 127;
    float creg = c0[(b0 + eb) * HDIM + eu];
    float hlast = 0.f;
    hbuf[eb * 128 + eu] = h0[(b0 + eb) * HDIM + eu];
    __syncthreads();

    /* P prefetch for t=0 */
    size_t ip = (size_t)b0 * G4;
    float p00 = g_P[ip + tid];
    float p01 = g_P[ip + 512 + tid];
    float p10 = g_P[ip + tid + 256];
    float p11 = g_P[ip + 512 + tid + 256];

    const ulonglong2* ws0 = (const ulonglong2*)(Wsm + tid * 68);
    const ulonglong2* ws1 = (const ulonglong2*)(Wsm + (tid + 256) * 68);

    for (int t = 0; t < T_STEPS; t++) {
        float q00 = p00, q01 = p01, q10 = p10, q11 = p11;
        ip += (size_t)BATCH * G4;
        if (t < T_STEPS - 1) {
            p00 = g_P[ip + tid];
            p01 = g_P[ip + 512 + tid];
            p10 = g_P[ip + tid + 256];
            p11 = g_P[ip + 512 + tid + 256];
        }

        const ulonglong2* hA = (const ulonglong2*)(hbuf + (t & 1) * 256);      /* b0 */
        const ulonglong2* hB = hA + 32;                                        /* b1 */

        ull a00 = 0ull, a01 = 0ull, a10 = 0ull, a11 = 0ull;

        /* k = 0..63 : weights in registers */
#pragma unroll
        for (int q = 0; q < 16; q++) {
            ulonglong2 ha = hA[q];
            ulonglong2 hb = hB[q];
            ffma2(a00, w0[2 * q],     ha.x); ffma2(a00, w0[2 * q + 1], ha.y);
            ffma2(a01, w0[2 * q],     hb.x); ffma2(a01, w0[2 * q + 1], hb.y);
            ffma2(a10, w1[2 * q],     ha.x); ffma2(a10, w1[2 * q + 1], ha.y);
            ffma2(a11, w1[2 * q],     hb.x); ffma2(a11, w1[2 * q + 1], hb.y);
        }
        /* k = 64..127 : weights in SMEM */
#pragma unroll
        for (int q = 0; q < 16; q++) {
            ulonglong2 ha = hA[16 + q];
            ulonglong2 hb = hB[16 + q];
            ulonglong2 wa = ws0[q];
            ulonglong2 wb = ws1[q];
            ffma2(a00, wa.x, ha.x); ffma2(a00, wa.y, ha.y);
            ffma2(a01, wa.x, hb.x); ffma2(a01, wa.y, hb.y);
            ffma2(a10, wb.x, ha.x); ffma2(a10, wb.y, ha.y);
            ffma2(a11, wb.x, hb.x); ffma2(a11, wb.y, hb.y);
        }

        *(float2*)&gsm[2 * tid]         = make_float2(q00 + hsum2(a00), q01 + hsum2(a01));
        *(float2*)&gsm[2 * (tid + 256)] = make_float2(q10 + hsum2(a10), q11 + hsum2(a11));
        __syncthreads();

        /* epilogue: each of the 256 threads owns one (batch, unit) */
        {
            float gi = gsm[2 * eu + eb];
            float gf = gsm[2 * (128 + eu) + eb];
            float gg = gsm[2 * (256 + eu) + eb];
            float go = gsm[2 * (384 + eu) + eb];
            float iv = 1.f / (1.f + __expf(-gi));
            float fv = 1.f / (1.f + __expf(-gf));
            float gv = tanhf(gg);
            float ov = 1.f / (1.f + __expf(-go));
            creg = fv * creg + iv * gv;
            float h = ov * tanhf(creg);
            hlast = h;
            hbuf[((t + 1) & 1) * 256 + eb * 128 + eu] = h;
            g_h[((size_t)t * BATCH + b0 + eb) * HDIM + eu] = h;
        }
        __syncthreads();
    }

    if (write_state) {
        state_out[(b0 + eb) * HDIM + eu] = hlast;
        state_out[BATCH * HDIM + (b0 + eb) * HDIM + eu] = creg;
    }
}

/* ------------------------------------------------------------------ */
/* Kernel 3: out = h_all @ fc_W^T + fc_b. One (t,b) row per thread.   */
/* f32x2 over k-pairs.                                                */
/* ------------------------------------------------------------------ */
__global__ __launch_bounds__(256) void k_fc(
    const float* __restrict__ fcW, const float* __restrict__ fcb,
    float* __restrict__ out)
{
    __shared__ float Ws[NCLS * HDIM];
    __shared__ float bs[NCLS];
    const int tid = threadIdx.x;
    for (int i = tid; i < NCLS * HDIM; i += 256) Ws[i] = fcW[i];
    if (tid < NCLS) bs[tid] = fcb[tid];
    __syncthreads();

    const size_t m = (size_t)blockIdx.x * 256 + tid;
    const ulonglong2* hv = (const ulonglong2*)(g_h + m * HDIM);

    ull acc[NCLS];
#pragma unroll
    for (int c = 0; c < NCLS; c++) acc[c] = 0ull;

#pragma unroll 2
    for (int q = 0; q < 32; q++) {
        ulonglong2 h = hv[q];
#pragma unroll
        for (int c = 0; c < NCLS; c++) {
            ulonglong2 w = *(const ulonglong2*)&Ws[c * HDIM + 4 * q];
            ffma2(acc[c], w.x, h.x);
            ffma2(acc[c], w.y, h.y);
        }
    }
    float* po = out + m * NCLS;
#pragma unroll
    for (int c = 0; c < NCLS; c++) po[c] = bs[c] + hsum2(acc[c]);
}

/* ------------------------------------------------------------------ */
extern "C" void kernel_launch(void* const* d_in, const int* in_sizes, int n_in,
                              void* d_out, int out_size)
{
    const float* X   = (const float*)d_in[0];
    const float* hid = (const float*)d_in[1];
    const float* cel = (const float*)d_in[2];
    const float* Wih = (const float*)d_in[3];
    const float* Whh = (const float*)d_in[4];
    const float* bih = (const float*)d_in[5];
    const float* bhh = (const float*)d_in[6];
    const float* fcW = (const float*)d_in[7];
    const float* fcb = (const float*)d_in[8];
    float* out = (float*)d_out;

    const int smem1 = 2 * 128 * 68 * 4;                       /* 69632  */
    const int smem2 = (512 * 68 + 512 + 1024) * 4;            /* 145408 */
    cudaFuncSetAttribute(k_input_gemm, cudaFuncAttributeMaxDynamicSharedMemorySize, smem1);
    cudaFuncSetAttribute(k_lstm,       cudaFuncAttributeMaxDynamicSharedMemorySize, smem2);

    k_input_gemm<<<dim3(G4 / 64, M_TOT / 64), 256, smem1>>>(X, Wih, bih, bhh);

    const int main_elems = T_STEPS * BATCH * NCLS;
    int wstate = (out_size >= main_elems + 2 * BATCH * HDIM) ? 1 : 0;
    float* state_out = out + (size_t)main_elems;
    k_lstm<<<BATCH / 2, 256, smem2>>>(hid, cel, Whh, state_out, wstate);

    k_fc<<<M_TOT / 256, 256>>>(fcW, fcb, out);
}

// round 5
// speedup vs baseline: 3.6605x; 1.0125x over previous
#include <cuda_runtime.h>
#include <cstdint>
#include <cstddef>

#define T_STEPS 1024
#define BATCH   256
#define IDIM    128
#define HDIM    128
#define NCLS    18
#define G4      (4*HDIM)              /* 512 */
#define M_TOT   (T_STEPS*BATCH)       /* 262144 */

typedef unsigned long long ull;

/* Scratch (allocation-free rule: __device__ globals). */
__device__ float g_P[(size_t)M_TOT * G4];   /* 512 MB pre-gates */
__device__ float g_h[(size_t)M_TOT * HDIM]; /* 128 MB h_all    */

/* packed f32x2 FMA: d = a*b + d  (two fp32 lanes per instruction) */
__device__ __forceinline__ void ffma2(ull& d, ull a, ull b) {
    asm("fma.rn.f32x2 %0, %1, %2, %0;" : "+l"(d) : "l"(a), "l"(b));
}
__device__ __forceinline__ float hsum2(ull v) {
    float2 f = *(float2*)&v;
    return f.x + f.y;
}
__device__ __forceinline__ ull dup2(float v) {
    ull r; asm("mov.b64 %0, {%1, %1};" : "=l"(r) : "f"(v)); return r;
}
/* accurate fast tanh: (e-1)/(e+1) with e = exp(2x); clamp avoids inf/inf */
__device__ __forceinline__ float fast_tanh(float x) {
    x = fminf(15.f, fmaxf(-15.f, x));
    float e = __expf(2.f * x);
    return (e - 1.f) * __frcp_rn(e + 1.f);
}
__device__ __forceinline__ float fast_sig(float x) {
    return __frcp_rn(1.f + __expf(-x));
}

/* ------------------------------------------------------------------ */
/* Kernel 1: P = X @ W_ih^T + (b_ih + b_hh).  M=262144, N=512, K=128. */
/* 64x64 tiles, packed f32x2 math (8 FFMA2 per k per thread).         */
/* ------------------------------------------------------------------ */
__global__ __launch_bounds__(256) void k_input_gemm(
    const float* __restrict__ X, const float* __restrict__ Wih,
    const float* __restrict__ bih, const float* __restrict__ bhh)
{
    extern __shared__ float sm1[];
    float* Xs = sm1;                 /* [128][68] k-major */
    float* Ws = sm1 + 128 * 68;      /* [128][68] k-major */

    const int tid = threadIdx.x;
    const int m0 = blockIdx.y * 64;
    const int n0 = blockIdx.x * 64;

    for (int idx = tid; idx < 64 * 128; idx += 256) {
        int r = idx >> 7, k = idx & 127;
        Xs[k * 68 + r] = X[(size_t)(m0 + r) * IDIM + k];
        Ws[k * 68 + r] = Wih[(size_t)(n0 + r) * IDIM + k];
    }
    __syncthreads();

    const int tx = tid & 15, ty = tid >> 4;
    ull acc[4][2];
#pragma unroll
    for (int i = 0; i < 4; i++) { acc[i][0] = 0ull; acc[i][1] = 0ull; }

#pragma unroll 8
    for (int k = 0; k < 128; k++) {
        float4 a = *(const float4*)&Xs[k * 68 + ty * 4];
        ulonglong2 b = *(const ulonglong2*)&Ws[k * 68 + tx * 4];
        ull ad[4] = {dup2(a.x), dup2(a.y), dup2(a.z), dup2(a.w)};
#pragma unroll
        for (int i = 0; i < 4; i++) {
            ffma2(acc[i][0], ad[i], b.x);
            ffma2(acc[i][1], ad[i], b.y);
        }
    }

    float bsv[4];
#pragma unroll
    for (int jj = 0; jj < 4; jj++)
        bsv[jj] = __ldg(&bih[n0 + tx * 4 + jj]) + __ldg(&bhh[n0 + tx * 4 + jj]);

#pragma unroll
    for (int i = 0; i < 4; i++) {
        float2 lo = *(float2*)&acc[i][0];
        float2 hi = *(float2*)&acc[i][1];
        float4 v = make_float4(lo.x + bsv[0], lo.y + bsv[1],
                               hi.x + bsv[2], hi.y + bsv[3]);
        *(float4*)&g_P[(size_t)(m0 + ty * 4 + i) * G4 + n0 + tx * 4] = v;
    }
}

/* ------------------------------------------------------------------ */
/* Kernel 2: recurrence. 128 CTAs x 256 threads; CTA owns 2 batches.  */
/* Thread tid owns gate rows tid and tid+256.                         */
/* W_hh k-pairs 0..47 (k=0..95) of BOTH rows in REGISTERS (192 regs), */
/* k-pairs 48..63 (k=96..127) in SMEM (stride 36 -> conflict-free).   */
/* ------------------------------------------------------------------ */
__global__ __launch_bounds__(256, 1) void k_lstm(
    const float* __restrict__ h0, const float* __restrict__ c0,
    const float* __restrict__ Whh, float* __restrict__ state_out,
    int write_state)
{
    extern __shared__ float sm2[];
    float* Wsm  = sm2;                  /* [512 rows][36]: k=96..127 (32 floats)  */
    float* hbuf = Wsm + 512 * 36;       /* [2 bufs][2 batch][128]                 */
    float* gsm  = hbuf + 512;           /* [512 rows][2 batch]                    */

    const int tid = threadIdx.x;
    const int b0  = blockIdx.x * 2;

    /* SMEM tail of W: rows 0..511, k = 96..127 */
    for (int idx = tid; idx < 512 * 8; idx += 256) {
        int row = idx >> 3, q = idx & 7;
        *(float4*)&Wsm[row * 36 + 4 * q] =
            *(const float4*)&Whh[(size_t)row * 128 + 96 + 4 * q];
    }

    /* register W: rows tid & tid+256, k-pairs 0..47 (k = 0..95) */
    ull w0[48], w1[48];
    {
        const ulonglong2* wg0 = (const ulonglong2*)(Whh + (size_t)tid * 128);
        const ulonglong2* wg1 = (const ulonglong2*)(Whh + (size_t)(tid + 256) * 128);
#pragma unroll
        for (int q = 0; q < 24; q++) {
            ulonglong2 t0 = wg0[q]; w0[2 * q] = t0.x; w0[2 * q + 1] = t0.y;
            ulonglong2 t1 = wg1[q]; w1[2 * q] = t1.x; w1[2 * q + 1] = t1.y;
        }
    }

    /* init h (smem buf 0) and c (register of epilogue-owner thread) */
    const int eb = tid >> 7, eu = tid & 127;
    float creg = c0[(b0 + eb) * HDIM + eu];
    float hlast = 0.f;
    hbuf[eb * 128 + eu] = h0[(b0 + eb) * HDIM + eu];
    __syncthreads();

    /* P prefetch for t=0 */
    size_t ip = (size_t)b0 * G4;
    float p00 = g_P[ip + tid];
    float p01 = g_P[ip + 512 + tid];
    float p10 = g_P[ip + tid + 256];
    float p11 = g_P[ip + 512 + tid + 256];

    const ulonglong2* ws0 = (const ulonglong2*)(Wsm + tid * 36);
    const ulonglong2* ws1 = (const ulonglong2*)(Wsm + (tid + 256) * 36);

    for (int t = 0; t < T_STEPS; t++) {
        float q00 = p00, q01 = p01, q10 = p10, q11 = p11;
        ip += (size_t)BATCH * G4;
        if (t < T_STEPS - 1) {
            p00 = g_P[ip + tid];
            p01 = g_P[ip + 512 + tid];
            p10 = g_P[ip + tid + 256];
            p11 = g_P[ip + 512 + tid + 256];
        }

        const ulonglong2* hA = (const ulonglong2*)(hbuf + (t & 1) * 256);  /* b0 */
        const ulonglong2* hB = hA + 32;                                    /* b1 */

        ull a00 = 0ull, a01 = 0ull, a10 = 0ull, a11 = 0ull;

        /* k-pairs 0..47 : weights in registers */
#pragma unroll
        for (int q = 0; q < 24; q++) {
            ulonglong2 ha = hA[q];
            ulonglong2 hb = hB[q];
            ffma2(a00, w0[2 * q],     ha.x); ffma2(a00, w0[2 * q + 1], ha.y);
            ffma2(a01, w0[2 * q],     hb.x); ffma2(a01, w0[2 * q + 1], hb.y);
            ffma2(a10, w1[2 * q],     ha.x); ffma2(a10, w1[2 * q + 1], ha.y);
            ffma2(a11, w1[2 * q],     hb.x); ffma2(a11, w1[2 * q + 1], hb.y);
        }
        /* k-pairs 48..63 : weights in SMEM */
#pragma unroll
        for (int q = 0; q < 8; q++) {
            ulonglong2 ha = hA[24 + q];
            ulonglong2 hb = hB[24 + q];
            ulonglong2 wa = ws0[q];
            ulonglong2 wb = ws1[q];
            ffma2(a00, wa.x, ha.x); ffma2(a00, wa.y, ha.y);
            ffma2(a01, wa.x, hb.x); ffma2(a01, wa.y, hb.y);
            ffma2(a10, wb.x, ha.x); ffma2(a10, wb.y, ha.y);
            ffma2(a11, wb.x, hb.x); ffma2(a11, wb.y, hb.y);
        }

        *(float2*)&gsm[2 * tid]         = make_float2(q00 + hsum2(a00), q01 + hsum2(a01));
        *(float2*)&gsm[2 * (tid + 256)] = make_float2(q10 + hsum2(a10), q11 + hsum2(a11));
        __syncthreads();

        /* epilogue: each of the 256 threads owns one (batch, unit) */
        {
            float gi = gsm[2 * eu + eb];
            float gf = gsm[2 * (128 + eu) + eb];
            float gg = gsm[2 * (256 + eu) + eb];
            float go = gsm[2 * (384 + eu) + eb];
            float iv = fast_sig(gi);
            float fv = fast_sig(gf);
            float gv = fast_tanh(gg);
            float ov = fast_sig(go);
            creg = fv * creg + iv * gv;
            float h = ov * fast_tanh(creg);
            hlast = h;
            hbuf[((t + 1) & 1) * 256 + eb * 128 + eu] = h;
            g_h[((size_t)t * BATCH + b0 + eb) * HDIM + eu] = h;
        }
        __syncthreads();
    }

    if (write_state) {
        state_out[(b0 + eb) * HDIM + eu] = hlast;
        state_out[BATCH * HDIM + (b0 + eb) * HDIM + eu] = creg;
    }
}

/* ------------------------------------------------------------------ */
/* Kernel 3: out = h_all @ fc_W^T + fc_b. One (t,b) row per thread.   */
/* ------------------------------------------------------------------ */
__global__ __launch_bounds__(256) void k_fc(
    const float* __restrict__ fcW, const float* __restrict__ fcb,
    float* __restrict__ out)
{
    __shared__ float Ws[NCLS * HDIM];
    __shared__ float bs[NCLS];
    const int tid = threadIdx.x;
    for (int i = tid; i < NCLS * HDIM; i += 256) Ws[i] = fcW[i];
    if (tid < NCLS) bs[tid] = fcb[tid];
    __syncthreads();

    const size_t m = (size_t)blockIdx.x * 256 + tid;
    const ulonglong2* hv = (const ulonglong2*)(g_h + m * HDIM);

    ull acc[NCLS];
#pragma unroll
    for (int c = 0; c < NCLS; c++) acc[c] = 0ull;

#pragma unroll 2
    for (int q = 0; q < 32; q++) {
        ulonglong2 h = hv[q];
#pragma unroll
        for (int c = 0; c < NCLS; c++) {
            ulonglong2 w = *(const ulonglong2*)&Ws[c * HDIM + 4 * q];
            ffma2(acc[c], w.x, h.x);
            ffma2(acc[c], w.y, h.y);
        }
    }
    float* po = out + m * NCLS;
#pragma unroll
    for (int c = 0; c < NCLS; c++) po[c] = bs[c] + hsum2(acc[c]);
}

/* ------------------------------------------------------------------ */
extern "C" void kernel_launch(void* const* d_in, const int* in_sizes, int n_in,
                              void* d_out, int out_size)
{
    const float* X   = (const float*)d_in[0];
    const float* hid = (const float*)d_in[1];
    const float* cel = (const float*)d_in[2];
    const float* Wih = (const float*)d_in[3];
    const float* Whh = (const float*)d_in[4];
    const float* bih = (const float*)d_in[5];
    const float* bhh = (const float*)d_in[6];
    const float* fcW = (const float*)d_in[7];
    const float* fcb = (const float*)d_in[8];
    float* out = (float*)d_out;

    const int smem1 = 2 * 128 * 68 * 4;                       /* 69632 */
    const int smem2 = (512 * 36 + 512 + 1024) * 4;            /* 79872 */
    cudaFuncSetAttribute(k_input_gemm, cudaFuncAttributeMaxDynamicSharedMemorySize, smem1);
    cudaFuncSetAttribute(k_lstm,       cudaFuncAttributeMaxDynamicSharedMemorySize, smem2);

    k_input_gemm<<<dim3(G4 / 64, M_TOT / 64), 256, smem1>>>(X, Wih, bih, bhh);

    const int main_elems = T_STEPS * BATCH * NCLS;
    int wstate = (out_size >= main_elems + 2 * BATCH * HDIM) ? 1 : 0;
    float* state_out = out + (size_t)main_elems;
    k_lstm<<<BATCH / 2, 256, smem2>>>(hid, cel, Whh, state_out, wstate);

    k_fc<<<M_TOT / 256, 256>>>(fcW, fcb, out);
}